// round 12
// baseline (speedup 1.0000x reference)
#include <cuda_runtime.h>
#include <cuda_bf16.h>
#include <math.h>

// Surv_Loss: sum over B rows of
//   status==1: -log(y_pred[i, y[i]])
//   status==0: -log(1 - sum_{j<y[i]} y_pred[i, j])
//
// Each warp owns 16 contiguous rows. Event rows (status==1) are handled
// LANE-PARALLEL (each lane gathers + logf its own row). Censored rows are
// handled in PAIRS: both rows' prefix loads issued up-front (MLP~10) and
// the two shuffle-reduce chains interleaved. Per-lane double accumulator,
// single warp reduce, fused deterministic last-block final reduction.

#define NBLOCKS 2048
#define THREADS 256
#define NWARPS  (THREADS / 32)
#define ROWS_PER_WARP 16

__device__ double       g_partials[NBLOCKS];
__device__ unsigned int g_count = 0;

__global__ __launch_bounds__(THREADS)
void surv_loss_kernel(const float* __restrict__ y_pred,
                      const int*   __restrict__ y,
                      const int*   __restrict__ status,
                      float*       __restrict__ out,
                      int B, int T) {
    const unsigned FULL = 0xFFFFFFFFu;
    const int lane  = threadIdx.x & 31;
    const int warp  = threadIdx.x >> 5;
    const int gwarp = blockIdx.x * NWARPS + warp;
    const int total_warps = NBLOCKS * NWARPS;      // 16384 warps * 16 rows = 262144

    double acc = 0.0;

    for (int base = gwarp * ROWS_PER_WARP; base < B;
         base += total_warps * ROWS_PER_WARP) {

        // ---- per-row metadata: lanes 0..15 each own one row (coalesced) ----
        const int myrow = base + lane;
        const bool meta = (lane < ROWS_PER_WARP) && (myrow < B);
        int v = 0, st = -1;
        if (meta) { v = __ldg(y + myrow); st = __ldg(status + myrow); }

        // ---- event rows: lane-parallel gather + log ----
        if (meta && st == 1) {
            float p = __ldg(y_pred + (size_t)myrow * (size_t)T + v);
            acc -= (double)logf(p);
        }

        // ---- censored rows: pairwise prefix sums ----
        unsigned cmask = __ballot_sync(FULL, meta && st == 0);
        while (cmask) {
            const int r0 = __ffs(cmask) - 1; cmask &= cmask - 1;
            int r1 = -1;
            if (cmask) { r1 = __ffs(cmask) - 1; cmask &= cmask - 1; }
            const bool has1 = (r1 >= 0);
            const int rr1 = has1 ? r1 : r0;

            const int v0 = __shfl_sync(FULL, v, r0);
            const int v1 = __shfl_sync(FULL, v, rr1);
            const float* rp0 = y_pred + (size_t)(base + r0)  * (size_t)T;
            const float* rp1 = y_pred + (size_t)(base + rr1) * (size_t)T;

            const int n40 = v0 >> 2;
            const int n41 = has1 ? (v1 >> 2) : 0;
            const float4* rp40 = reinterpret_cast<const float4*>(rp0);
            const float4* rp41 = reinterpret_cast<const float4*>(rp1);

            // issue all loads for BOTH rows before any arithmetic (MLP<=10)
            float4 z = make_float4(0.f, 0.f, 0.f, 0.f);
            float4 a0 = z, a1 = z, a2 = z, a3 = z;
            float4 b0 = z, b1 = z, b2 = z, b3 = z;
            if (lane      < n40) a0 = __ldg(rp40 + lane);
            if (lane + 32 < n40) a1 = __ldg(rp40 + lane + 32);
            if (lane + 64 < n40) a2 = __ldg(rp40 + lane + 64);
            if (lane + 96 < n40) a3 = __ldg(rp40 + lane + 96);
            if (lane      < n41) b0 = __ldg(rp41 + lane);
            if (lane + 32 < n41) b1 = __ldg(rp41 + lane + 32);
            if (lane + 64 < n41) b2 = __ldg(rp41 + lane + 64);
            if (lane + 96 < n41) b3 = __ldg(rp41 + lane + 96);
            float t0 = 0.f, t1 = 0.f;
            if (lane < (v0 & 3))          t0 = __ldg(rp0 + (n40 << 2) + lane);
            if (has1 && lane < (v1 & 3))  t1 = __ldg(rp1 + (n41 << 2) + lane);

            float s0 = ((a0.x + a0.y) + (a0.z + a0.w))
                     + ((a1.x + a1.y) + (a1.z + a1.w))
                     + ((a2.x + a2.y) + (a2.z + a2.w))
                     + ((a3.x + a3.y) + (a3.z + a3.w)) + t0;
            float s1 = ((b0.x + b0.y) + (b0.z + b0.w))
                     + ((b1.x + b1.y) + (b1.z + b1.w))
                     + ((b2.x + b2.y) + (b2.z + b2.w))
                     + ((b3.x + b3.y) + (b3.z + b3.w)) + t1;

            // two independent shuffle-reduce chains, interleaved
            #pragma unroll
            for (int off = 16; off > 0; off >>= 1) {
                s0 += __shfl_down_sync(FULL, s0, off);
                s1 += __shfl_down_sync(FULL, s1, off);
            }
            if (lane == 0) {
                acc -= (double)logf(1.0f - s0);
                if (has1) acc -= (double)logf(1.0f - s1);
            }
        }
    }

    // ---- warp reduce per-lane double accumulators ----
    #pragma unroll
    for (int off = 16; off > 0; off >>= 1)
        acc += __shfl_down_sync(FULL, acc, off);

    // ---- block partial + fused deterministic last-block reduction ----
    __shared__ double sh[THREADS];
    __shared__ bool   am_last;

    if (lane == 0) sh[warp] = acc;
    __syncthreads();

    if (threadIdx.x == 0) {
        double bs = 0.0;
        #pragma unroll
        for (int w = 0; w < NWARPS; ++w) bs += sh[w];
        g_partials[blockIdx.x] = bs;
        __threadfence();
        unsigned int t = atomicAdd(&g_count, 1u);
        am_last = (t == (unsigned int)(gridDim.x - 1));
    }
    __syncthreads();

    if (am_last) {
        double s = 0.0;
        for (int i = threadIdx.x; i < NBLOCKS; i += THREADS)
            s += g_partials[i];              // fixed order per thread
        __syncthreads();
        sh[threadIdx.x] = s;
        __syncthreads();
        for (int off = THREADS / 2; off > 0; off >>= 1) {
            if (threadIdx.x < off) sh[threadIdx.x] += sh[threadIdx.x + off];
            __syncthreads();
        }
        if (threadIdx.x == 0) {
            out[0] = (float)sh[0];
            g_count = 0;                     // reset for next graph replay
        }
    }
}

extern "C" void kernel_launch(void* const* d_in, const int* in_sizes, int n_in,
                              void* d_out, int out_size) {
    const float* y_pred = (const float*)d_in[0];
    const int*   y      = (const int*)d_in[1];
    const int*   status = (const int*)d_in[2];
    float* out = (float*)d_out;

    const int B = in_sizes[1];
    const int T = in_sizes[0] / B;

    surv_loss_kernel<<<NBLOCKS, THREADS>>>(y_pred, y, status, out, B, T);
}